// round 2
// baseline (speedup 1.0000x reference)
#include <cuda_runtime.h>
#include <math_constants.h>

#define QT      8
#define TK      1024
#define TQ      1024
#define D       64
#define THREADS 256

__device__ __forceinline__ float fast_tanh(float x) {
    float y;
    asm("tanh.approx.f32 %0, %1;" : "=f"(y) : "f"(x));
    return y;
}

__global__ __launch_bounds__(THREADS, 2)
void addattn_kernel(const float* __restrict__ q,
                    const float* __restrict__ v,
                    const float* __restrict__ scale,
                    float* __restrict__ out)
{
    __shared__ float qs[QT][D];          // 2 KB   q tile
    __shared__ float ss[D];              // 256 B  scale
    __shared__ float sc[QT][TK];         // 32 KB  scores -> probs
    __shared__ float rsum[QT];           // 32 B   1/sum per q row
    __shared__ float part[4][QT][D];     // 8 KB   pass-2 partials

    const int tid = threadIdx.x;
    const int b  = blockIdx.x >> 7;              // 128 q-blocks per batch
    const int q0 = (blockIdx.x & 127) * QT;

    const float* qbase = q + ((size_t)b * TQ + q0) * D;
    const float* vbase = v + (size_t)b * TK * D;

    // ---- stage q tile + scale into smem ----
    for (int i = tid; i < QT * D; i += THREADS) qs[i / D][i % D] = qbase[i];
    if (tid < D) ss[tid] = scale[tid];
    __syncthreads();

    // ---- pass 1: scores[q][k] = sum_d scale[d]*tanh(q[q][d] + v[k][d]) ----
    // d4 outer / qi inner: V row chunk + scale chunk stay in registers across
    // all 8 q rows -> 16 LDG.128 per k-column instead of 128.
    const float4* s4 = (const float4*)ss;
    #pragma unroll
    for (int kk = 0; kk < TK / THREADS; kk++) {
        const int k = kk * THREADS + tid;
        const float4* vrow = (const float4*)(vbase + (size_t)k * D);

        float acc[QT];
        #pragma unroll
        for (int qi = 0; qi < QT; qi++) acc[qi] = 0.f;

        #pragma unroll
        for (int d4 = 0; d4 < D / 4; d4++) {
            const float4 vv = vrow[d4];   // 1 LDG.128, L2-resident
            const float4 sv = s4[d4];     // smem broadcast
            #pragma unroll
            for (int qi = 0; qi < QT; qi++) {
                const float4 qq = ((const float4*)qs[qi])[d4];  // smem broadcast
                float a = acc[qi];
                a += sv.x * fast_tanh(qq.x + vv.x);
                a += sv.y * fast_tanh(qq.y + vv.y);
                a += sv.z * fast_tanh(qq.z + vv.z);
                a += sv.w * fast_tanh(qq.w + vv.w);
                acc[qi] = a;
            }
        }
        #pragma unroll
        for (int qi = 0; qi < QT; qi++) sc[qi][k] = acc[qi];
    }
    __syncthreads();

    // ---- softmax: warp w handles q-row w ----
    const int wid  = tid >> 5;
    const int lane = tid & 31;
    {
        float m = -CUDART_INF_F;
        #pragma unroll 4
        for (int k = lane; k < TK; k += 32) m = fmaxf(m, sc[wid][k]);
        #pragma unroll
        for (int o = 16; o; o >>= 1) m = fmaxf(m, __shfl_xor_sync(0xffffffffu, m, o));
        float s = 0.f;
        #pragma unroll 4
        for (int k = lane; k < TK; k += 32) {
            float p = __expf(sc[wid][k] - m);   // MUFU.EX2
            sc[wid][k] = p;
            s += p;
        }
        #pragma unroll
        for (int o = 16; o; o >>= 1) s += __shfl_xor_sync(0xffffffffu, s, o);
        if (lane == 0) rsum[wid] = 1.f / s;
    }
    __syncthreads();

    // ---- pass 2: out[q][d] = (1/sum) * sum_k p[q][k] * v[k][d] ----
    const int d = tid & 63;
    const int g = tid >> 6;        // k-quarter 0..3
    float acc[QT];
    #pragma unroll
    for (int qi = 0; qi < QT; qi++) acc[qi] = 0.f;

    for (int k = g; k < TK; k += 4) {
        float vv = vbase[(size_t)k * D + d];   // coalesced 128B per warp
        #pragma unroll
        for (int qi = 0; qi < QT; qi++)
            acc[qi] += sc[qi][k] * vv;          // smem broadcast within warp
    }
    #pragma unroll
    for (int qi = 0; qi < QT; qi++) part[g][qi][d] = acc[qi];
    __syncthreads();

    // cross-quarter reduce: thread (g,d) finalizes rows g and g+4
    int qi = g;
    #pragma unroll
    for (int h = 0; h < 2; h++, qi += 4) {
        float r = part[0][qi][d] + part[1][qi][d] + part[2][qi][d] + part[3][qi][d];
        out[((size_t)b * TQ + q0 + qi) * D + d] = r * rsum[qi];
    }
}

extern "C" void kernel_launch(void* const* d_in, const int* in_sizes, int n_in,
                              void* d_out, int out_size)
{
    const float* query = (const float*)d_in[0];
    const float* value = (const float*)d_in[1];
    const float* scale = (const float*)d_in[2];
    float* out = (float*)d_out;

    dim3 grid(2 * TQ / QT);   // 256 blocks
    dim3 block(THREADS);
    addattn_kernel<<<grid, block>>>(query, value, scale, out);
}

// round 3
// speedup vs baseline: 2.9943x; 2.9943x over previous
#include <cuda_runtime.h>
#include <math_constants.h>

#define QT      8
#define TK      1024
#define TQ      1024
#define D       64
#define THREADS 256

__device__ __forceinline__ float fast_tanh(float x) {
    float y;
    asm("tanh.approx.f32 %0, %1;" : "=f"(y) : "f"(x));
    return y;
}

// minBlocksPerMultiprocessor=4 forces ptxas to <=64 regs -> 4 CTAs/SM (occ ~42%)
__global__ __launch_bounds__(THREADS, 4)
void addattn_kernel(const float* __restrict__ q,
                    const float* __restrict__ v,
                    const float* __restrict__ scale,
                    float* __restrict__ out)
{
    __shared__ float qs[QT][D];          // 2 KB   q tile
    __shared__ float ss[D];              // 256 B  scale
    __shared__ float sc[QT][TK];         // 32 KB  scores -> probs
    __shared__ float rsum[QT];           // 32 B   1/sum per q row
    __shared__ float part[4][QT][D];     // 8 KB   pass-2 partials

    const int tid = threadIdx.x;
    const int b  = blockIdx.x >> 7;              // 128 q-blocks per batch
    const int q0 = (blockIdx.x & 127) * QT;

    const float* qbase = q + ((size_t)b * TQ + q0) * D;
    const float* vbase = v + (size_t)b * TK * D;

    // ---- stage q tile + scale into smem ----
    for (int i = tid; i < QT * D; i += THREADS) qs[i / D][i % D] = qbase[i];
    if (tid < D) ss[tid] = scale[tid];
    __syncthreads();

    // ---- pass 1: scores[q][k] = sum_d scale[d]*tanh(q[q][d] + v[k][d]) ----
    // kk NOT unrolled + d4 unrolled x4: keeps live LDG batch small (16 regs of
    // vv instead of 64) so the kernel fits 64 regs and runs 4 CTAs/SM.
    const float4* s4 = (const float4*)ss;
    #pragma unroll 1
    for (int kk = 0; kk < TK / THREADS; kk++) {
        const int k = kk * THREADS + tid;
        const float4* vrow = (const float4*)(vbase + (size_t)k * D);

        float acc[QT];
        #pragma unroll
        for (int qi = 0; qi < QT; qi++) acc[qi] = 0.f;

        #pragma unroll 4
        for (int d4 = 0; d4 < D / 4; d4++) {
            const float4 vv = vrow[d4];   // L1/L2-resident
            const float4 sv = s4[d4];     // smem broadcast
            #pragma unroll
            for (int qi = 0; qi < QT; qi++) {
                const float4 qq = ((const float4*)qs[qi])[d4];  // smem broadcast
                float a = acc[qi];
                a += sv.x * fast_tanh(qq.x + vv.x);
                a += sv.y * fast_tanh(qq.y + vv.y);
                a += sv.z * fast_tanh(qq.z + vv.z);
                a += sv.w * fast_tanh(qq.w + vv.w);
                acc[qi] = a;
            }
        }
        #pragma unroll
        for (int qi = 0; qi < QT; qi++) sc[qi][k] = acc[qi];
    }
    __syncthreads();

    // ---- softmax: warp w handles q-row w ----
    const int wid  = tid >> 5;
    const int lane = tid & 31;
    {
        float m = -CUDART_INF_F;
        #pragma unroll 4
        for (int k = lane; k < TK; k += 32) m = fmaxf(m, sc[wid][k]);
        #pragma unroll
        for (int o = 16; o; o >>= 1) m = fmaxf(m, __shfl_xor_sync(0xffffffffu, m, o));
        float s = 0.f;
        #pragma unroll 4
        for (int k = lane; k < TK; k += 32) {
            float p = __expf(sc[wid][k] - m);   // MUFU.EX2
            sc[wid][k] = p;
            s += p;
        }
        #pragma unroll
        for (int o = 16; o; o >>= 1) s += __shfl_xor_sync(0xffffffffu, s, o);
        if (lane == 0) rsum[wid] = 1.f / s;
    }
    __syncthreads();

    // ---- pass 2: out[q][d] = (1/sum) * sum_k p[q][k] * v[k][d] ----
    const int d = tid & 63;
    const int g = tid >> 6;        // k-quarter 0..3
    float acc[QT];
    #pragma unroll
    for (int qi = 0; qi < QT; qi++) acc[qi] = 0.f;

    #pragma unroll 4
    for (int k = g; k < TK; k += 4) {
        float vv = vbase[(size_t)k * D + d];   // coalesced 128B per warp
        #pragma unroll
        for (int qi = 0; qi < QT; qi++)
            acc[qi] += sc[qi][k] * vv;          // smem broadcast within warp
    }
    #pragma unroll
    for (int qi = 0; qi < QT; qi++) part[g][qi][d] = acc[qi];
    __syncthreads();

    // cross-quarter reduce: thread (g,d) finalizes rows g and g+4
    int qi = g;
    #pragma unroll
    for (int h = 0; h < 2; h++, qi += 4) {
        float r = part[0][qi][d] + part[1][qi][d] + part[2][qi][d] + part[3][qi][d];
        out[((size_t)b * TQ + q0 + qi) * D + d] = r * rsum[qi];
    }
}

extern "C" void kernel_launch(void* const* d_in, const int* in_sizes, int n_in,
                              void* d_out, int out_size)
{
    const float* query = (const float*)d_in[0];
    const float* value = (const float*)d_in[1];
    const float* scale = (const float*)d_in[2];
    float* out = (float*)d_out;

    dim3 grid(2 * TQ / QT);   // 256 blocks
    dim3 block(THREADS);
    addattn_kernel<<<grid, block>>>(query, value, scale, out);
}